// round 1
// baseline (speedup 1.0000x reference)
#include <cuda_runtime.h>
#include <cuda_bf16.h>
#include <math.h>

#define NA 8400
#define BSZ 32
#define NM 32
#define NC 80
#define TOPK 9
#define NPAIR (BSZ*NM)

__device__ unsigned int g_maskpos[BSZ * NA];

__global__ void k_zero() {
    int i = blockIdx.x * blockDim.x + threadIdx.x;
    if (i < BSZ * NA) g_maskpos[i] = 0u;
}

// One block (256 thr) per (b,g) gt pair: top-9 per level by distance,
// candidate IoU stats -> threshold -> set gt bit on positive anchors.
__global__ __launch_bounds__(256) void k_pairs(
    const float* __restrict__ anc,
    const float* __restrict__ gtb,
    const float* __restrict__ mask_gt)
{
    __shared__ float rd[256];
    __shared__ int   ri[256];
    __shared__ int   cand[27];
    __shared__ float sov[27];
    __shared__ float s_thr;

    const int p = blockIdx.x;
    const int b = p >> 5;
    const int g = p & 31;
    if (mask_gt[p] <= 0.0f) return;   // uniform across block

    const float4 gt = ((const float4*)gtb)[p];
    const float gx = (gt.x + gt.z) * 0.5f;
    const float gy = (gt.y + gt.w) * 0.5f;
    const int tid = threadIdx.x;

    const int starts[3] = {0, 6400, 8000};
    const int lens[3]   = {6400, 1600, 400};

    for (int lvl = 0; lvl < 3; ++lvl) {
        float ld[TOPK]; int li[TOPK];
        #pragma unroll
        for (int j = 0; j < TOPK; ++j) { ld[j] = 3.0e38f; li[j] = 0x7fffffff; }
        float worst = 3.0e38f;

        const int start = starts[lvl], L = lens[lvl];
        for (int al = tid; al < L; al += 256) {
            const int a = start + al;
            const float4 ab = ((const float4*)anc)[a];
            const float ax = (ab.x + ab.z) * 0.5f;
            const float ay = (ab.y + ab.w) * 0.5f;
            const float dx = gx - ax, dy = gy - ay;
            const float d = sqrtf(dx * dx + dy * dy);   // match reference sqrt rounding
            if (d < worst) {
                int pos = TOPK - 1;
                while (pos > 0 && d < ld[pos - 1]) {
                    ld[pos] = ld[pos - 1]; li[pos] = li[pos - 1]; --pos;
                }
                ld[pos] = d; li[pos] = a;
                worst = ld[TOPK - 1];
            }
        }

        // 9 rounds of block argmin over per-thread sorted heads
        int h = 0;
        for (int r = 0; r < TOPK; ++r) {
            const float hd = (h < TOPK) ? ld[h] : 3.0e38f;
            const int   hi = (h < TOPK) ? li[h] : 0x7fffffff;
            rd[tid] = hd; ri[tid] = hi;
            __syncthreads();
            for (int s = 128; s > 0; s >>= 1) {
                if (tid < s) {
                    const float od = rd[tid + s]; const int oi = ri[tid + s];
                    if (od < rd[tid] || (od == rd[tid] && oi < ri[tid])) {
                        rd[tid] = od; ri[tid] = oi;
                    }
                }
                __syncthreads();
            }
            const float wd = rd[0]; const int wi = ri[0];
            if (hd == wd && hi == wi) ++h;        // unique (d,idx): single winner
            if (tid == 0) cand[lvl * TOPK + r] = wi;
            __syncthreads();
        }
    }

    // candidate overlaps (exact _iou2d: no area clip, union eps 1e-6)
    if (tid < 27) {
        const int a = cand[tid];
        const float4 ab = ((const float4*)anc)[a];
        const float area1 = (gt.z - gt.x) * (gt.w - gt.y);
        const float area2 = (ab.z - ab.x) * (ab.w - ab.y);
        const float ltx = fmaxf(gt.x, ab.x), lty = fmaxf(gt.y, ab.y);
        const float rbx = fminf(gt.z, ab.z), rby = fminf(gt.w, ab.w);
        const float w = fmaxf(rbx - ltx, 0.0f), hh = fmaxf(rby - lty, 0.0f);
        const float ov = w * hh;
        const float un = fmaxf(area1 + area2 - ov, 1e-6f);
        sov[tid] = ov / un;
    }
    __syncthreads();
    if (tid == 0) {
        float s = 0.0f;
        for (int j = 0; j < 27; ++j) s += sov[j];
        const float mean = s * (1.0f / 27.0f);
        float v = 0.0f;
        for (int j = 0; j < 27; ++j) { const float d = sov[j] - mean; v += d * d; }
        s_thr = mean + sqrtf(v * (1.0f / 26.0f));   // ddof=1
    }
    __syncthreads();
    if (tid < 27 && sov[tid] > s_thr) {
        const int a = cand[tid];
        const float4 ab = ((const float4*)anc)[a];
        const float ax = (ab.x + ab.z) * 0.5f;
        const float ay = (ab.y + ab.w) * 0.5f;
        const float mn = fminf(fminf(ax - gt.x, ay - gt.y),
                               fminf(gt.z - ax, gt.w - ay));
        if (mn > 1e-9f) atomicOr(&g_maskpos[b * NA + a], 1u << g);
    }
}

// One thread per (b, anchor): resolve multi-assignment, write all outputs.
__global__ __launch_bounds__(256) void k_assign(
    const float* __restrict__ anc,
    const int*   __restrict__ gt_labels,
    const float* __restrict__ gtb,
    const float* __restrict__ pd,
    float* __restrict__ o_lab,
    float* __restrict__ o_box,
    float* __restrict__ o_scr,
    float* __restrict__ o_fg)
{
    const int idx = blockIdx.x * blockDim.x + threadIdx.x;
    if (idx >= BSZ * NA) return;
    const int b = idx / NA;
    const int a = idx - b * NA;

    const unsigned int m = g_maskpos[idx];
    const int cnt = __popc(m);
    int tgt = 0;
    const bool fg = (cnt > 0);

    if (cnt == 1) {
        tgt = __ffs(m) - 1;
    } else if (cnt > 1) {
        // argmax over g of overlaps (full, unmasked), first-occurrence ties
        const float4 ab = ((const float4*)anc)[a];
        const float area2 = (ab.z - ab.x) * (ab.w - ab.y);
        float best = -1.0f;
        for (int gg = 0; gg < NM; ++gg) {
            const float4 gb = ((const float4*)gtb)[b * NM + gg];
            const float area1 = (gb.z - gb.x) * (gb.w - gb.y);
            const float ltx = fmaxf(gb.x, ab.x), lty = fmaxf(gb.y, ab.y);
            const float rbx = fminf(gb.z, ab.z), rby = fminf(gb.w, ab.w);
            const float w = fmaxf(rbx - ltx, 0.0f), hh = fmaxf(rby - lty, 0.0f);
            const float ov = w * hh;
            const float un = fmaxf(area1 + area2 - ov, 1e-6f);
            const float v = ov / un;
            if (v > best) { best = v; tgt = gg; }
        }
    }

    const int label = fg ? gt_labels[b * NM + tgt] : NC;
    const float4 tb = ((const float4*)gtb)[b * NM + tgt];

    o_lab[idx] = (float)label;
    ((float4*)o_box)[idx] = tb;
    o_fg[idx] = fg ? 1.0f : 0.0f;

    float score = 0.0f;
    if (fg) {
        // _iou_batched: clipped areas, eps 1e-9 added (no max)
        const float4 pb = ((const float4*)pd)[(size_t)b * NA + a];
        const float iw = fmaxf(fminf(tb.z, pb.z) - fmaxf(tb.x, pb.x), 0.0f);
        const float ih = fmaxf(fminf(tb.w, pb.w) - fmaxf(tb.y, pb.y), 0.0f);
        const float ov = iw * ih;
        const float a1 = fmaxf(tb.z - tb.x, 0.0f) * fmaxf(tb.w - tb.y, 0.0f);
        const float a2 = fmaxf(pb.z - pb.x, 0.0f) * fmaxf(pb.w - pb.y, 0.0f);
        score = ov / (a1 + a2 - ov + 1e-9f);
    }

    // dense 80-float score row: zeros, one nonzero at label for fg
    float4* srow = (float4*)(o_scr + (size_t)idx * NC);
    const float4 z = make_float4(0.0f, 0.0f, 0.0f, 0.0f);
    #pragma unroll
    for (int j = 0; j < NC / 4; ++j) srow[j] = z;
    if (fg) o_scr[(size_t)idx * NC + label] = score;
}

extern "C" void kernel_launch(void* const* d_in, const int* in_sizes, int n_in,
                              void* d_out, int out_size)
{
    const float* anc = (const float*)d_in[0];   // [8400,4]
    const int*   gtl = (const int*)  d_in[1];   // [32,32,1]
    const float* gtb = (const float*)d_in[2];   // [32,32,4]
    const float* mgt = (const float*)d_in[3];   // [32,32,1]
    const float* pd  = (const float*)d_in[4];   // [32,8400,4]

    float* out   = (float*)d_out;
    float* o_lab = out;                               // 268800
    float* o_box = o_lab + (size_t)BSZ * NA;          // 1075200
    float* o_scr = o_box + (size_t)BSZ * NA * 4;      // 21504000
    float* o_fg  = o_scr + (size_t)BSZ * NA * NC;     // 268800

    k_zero<<<(BSZ * NA + 255) / 256, 256>>>();
    k_pairs<<<NPAIR, 256>>>(anc, gtb, mgt);
    k_assign<<<(BSZ * NA + 255) / 256, 256>>>(anc, gtl, gtb, pd,
                                              o_lab, o_box, o_scr, o_fg);
}

// round 3
// speedup vs baseline: 1.3800x; 1.3800x over previous
#include <cuda_runtime.h>
#include <cuda_bf16.h>
#include <math.h>

#define NA 8400
#define BSZ 32
#define NM 32
#define NC 80
#define TOPK 9

__device__ unsigned int g_maskpos[BSZ * NA];
__device__ float2       g_ac[NA];               // anchor centers

// Zero score region (float4-coalesced), zero gt bitmask, compute centers.
__global__ __launch_bounds__(256) void k_prep(
    const float* __restrict__ anc, float4* __restrict__ scr4)
{
    const int i = blockIdx.x * blockDim.x + threadIdx.x;
    const int NS4 = BSZ * NA * NC / 4;          // 5,376,000
    if (i < NS4) scr4[i] = make_float4(0.f, 0.f, 0.f, 0.f);
    if (i < BSZ * NA / 4) ((uint4*)g_maskpos)[i] = make_uint4(0u, 0u, 0u, 0u);
    if (i < NA) {
        const float4 ab = ((const float4*)anc)[i];
        g_ac[i] = make_float2((ab.x + ab.z) * 0.5f, (ab.y + ab.w) * 0.5f);
    }
}

// One WARP per (b,g) pair; 8 warps/block (centers shared via L1).
__global__ __launch_bounds__(256) void k_pairs(
    const float* __restrict__ anc,
    const float* __restrict__ gtb,
    const float* __restrict__ mask_gt)
{
    const int tid  = threadIdx.x;
    const int lane = tid & 31;
    const int w    = tid >> 5;

    const int p = blockIdx.x * 8 + w;
    const int b = p >> 5;
    const int g = p & 31;
    if (mask_gt[p] <= 0.0f) return;             // warp-uniform

    const float4 gt = ((const float4*)gtb)[p];
    const float gx = (gt.x + gt.z) * 0.5f;
    const float gy = (gt.y + gt.w) * 0.5f;

    const int starts[3] = {0, 6400, 8000};
    const int lens[3]   = {6400, 1600, 400};

    int cand[27];

    for (int lvl = 0; lvl < 3; ++lvl) {
        // Per-lane sorted top-9 as packed u64 keys (static indices -> registers)
        unsigned long long kk[TOPK];
        #pragma unroll
        for (int j = 0; j < TOPK; ++j) kk[j] = 0xFFFFFFFFFFFFFFFFull;

        const int start = starts[lvl], L = lens[lvl];
        for (int al = lane; al < L; al += 32) {
            const float2 c = g_ac[start + al];
            const float dx = gx - c.x, dy = gy - c.y;
            const float d = sqrtf(dx * dx + dy * dy);
            const unsigned long long key =
                ((unsigned long long)__float_as_uint(d) << 32) |
                (unsigned int)(start + al);
            if (key < kk[TOPK - 1]) {
                kk[TOPK - 1] = key;
                #pragma unroll
                for (int j = TOPK - 1; j > 0; --j) {
                    if (kk[j] < kk[j - 1]) {
                        const unsigned long long t = kk[j - 1];
                        kk[j - 1] = kk[j]; kk[j] = t;
                    }
                }
            }
        }

        // 9 rounds of warp-wide u64 min; winning lane pops its head.
        #pragma unroll
        for (int r = 0; r < TOPK; ++r) {
            const unsigned long long v = kk[0];
            unsigned long long m = v;
            #pragma unroll
            for (int s = 16; s > 0; s >>= 1) {
                const unsigned long long o = __shfl_xor_sync(0xffffffffu, m, s);
                if (o < m) m = o;
            }
            if (v == m) {                        // idx bits make keys unique
                #pragma unroll
                for (int j = 0; j < TOPK - 1; ++j) kk[j] = kk[j + 1];
                kk[TOPK - 1] = 0xFFFFFFFFFFFFFFFFull;
            }
            cand[lvl * TOPK + r] = (int)(unsigned int)m;   // uniform across warp
        }
    }

    // Candidate overlaps (_iou2d: unclipped areas, union eps 1e-6)
    float ov = 0.0f;
    int ca = 0;
    float4 ab = make_float4(0.f, 0.f, 0.f, 0.f);
    if (lane < 27) {
        ca = cand[lane];                         // lane-indexed: dynamic but small
        // avoid local-mem dynamic index: select via shuffle instead
    }
    // broadcast cand[] through shuffles to avoid per-thread array indexing costs:
    // simpler: each lane<27 re-computes from registers is not possible; use smem.
    __shared__ int s_cand[8][27];
    #pragma unroll
    for (int j = 0; j < 27; ++j) if (lane == 0) s_cand[w][j] = cand[j];
    __syncwarp();
    if (lane < 27) {
        ca = s_cand[w][lane];
        ab = ((const float4*)anc)[ca];
        const float area1 = (gt.z - gt.x) * (gt.w - gt.y);
        const float area2 = (ab.z - ab.x) * (ab.w - ab.y);
        const float ltx = fmaxf(gt.x, ab.x), lty = fmaxf(gt.y, ab.y);
        const float rbx = fminf(gt.z, ab.z), rby = fminf(gt.w, ab.w);
        const float ww = fmaxf(rbx - ltx, 0.0f), hh = fmaxf(rby - lty, 0.0f);
        const float o = ww * hh;
        ov = o / fmaxf(area1 + area2 - o, 1e-6f);
    }

    // mean + std(ddof=1) threshold via warp sums
    float s = (lane < 27) ? ov : 0.0f;
    #pragma unroll
    for (int sft = 16; sft > 0; sft >>= 1) s += __shfl_xor_sync(0xffffffffu, s, sft);
    const float mean = s * (1.0f / 27.0f);
    float dv = (lane < 27) ? (ov - mean) * (ov - mean) : 0.0f;
    #pragma unroll
    for (int sft = 16; sft > 0; sft >>= 1) dv += __shfl_xor_sync(0xffffffffu, dv, sft);
    const float thr = mean + sqrtf(dv * (1.0f / 26.0f));

    if (lane < 27 && ov > thr) {
        const float ax = (ab.x + ab.z) * 0.5f;
        const float ay = (ab.y + ab.w) * 0.5f;
        const float mn = fminf(fminf(ax - gt.x, ay - gt.y),
                               fminf(gt.z - ax, gt.w - ay));
        if (mn > 1e-9f) atomicOr(&g_maskpos[b * NA + ca], 1u << g);
    }
}

// One thread per (b, anchor): resolve multi-assignment, write outputs.
// Score rows pre-zeroed by k_prep; only scatter the fg nonzero.
__global__ __launch_bounds__(256) void k_assign(
    const float* __restrict__ anc,
    const int*   __restrict__ gt_labels,
    const float* __restrict__ gtb,
    const float* __restrict__ pd,
    float* __restrict__ o_lab,
    float* __restrict__ o_box,
    float* __restrict__ o_scr,
    float* __restrict__ o_fg)
{
    const int idx = blockIdx.x * blockDim.x + threadIdx.x;
    if (idx >= BSZ * NA) return;
    const int b = idx / NA;
    const int a = idx - b * NA;

    const unsigned int m = g_maskpos[idx];
    const int cnt = __popc(m);
    int tgt = 0;
    const bool fg = (cnt > 0);

    if (cnt == 1) {
        tgt = __ffs(m) - 1;
    } else if (cnt > 1) {
        // argmax over gts of full overlaps (first-occurrence ties)
        const float4 ab = ((const float4*)anc)[a];
        const float area2 = (ab.z - ab.x) * (ab.w - ab.y);
        float best = -1.0f;
        for (int gg = 0; gg < NM; ++gg) {
            const float4 gb = ((const float4*)gtb)[b * NM + gg];
            const float area1 = (gb.z - gb.x) * (gb.w - gb.y);
            const float ltx = fmaxf(gb.x, ab.x), lty = fmaxf(gb.y, ab.y);
            const float rbx = fminf(gb.z, ab.z), rby = fminf(gb.w, ab.w);
            const float w = fmaxf(rbx - ltx, 0.0f), hh = fmaxf(rby - lty, 0.0f);
            const float ovv = w * hh;
            const float v = ovv / fmaxf(area1 + area2 - ovv, 1e-6f);
            if (v > best) { best = v; tgt = gg; }
        }
    }

    const int label = fg ? gt_labels[b * NM + tgt] : NC;
    const float4 tb = ((const float4*)gtb)[b * NM + tgt];

    o_lab[idx] = (float)label;
    ((float4*)o_box)[idx] = tb;
    o_fg[idx] = fg ? 1.0f : 0.0f;

    if (fg) {
        // _iou_batched: clipped areas, +1e-9 in denominator
        const float4 pb = ((const float4*)pd)[(size_t)b * NA + a];
        const float iw = fmaxf(fminf(tb.z, pb.z) - fmaxf(tb.x, pb.x), 0.0f);
        const float ih = fmaxf(fminf(tb.w, pb.w) - fmaxf(tb.y, pb.y), 0.0f);
        const float ovv = iw * ih;
        const float a1 = fmaxf(tb.z - tb.x, 0.0f) * fmaxf(tb.w - tb.y, 0.0f);
        const float a2 = fmaxf(pb.z - pb.x, 0.0f) * fmaxf(pb.w - pb.y, 0.0f);
        o_scr[(size_t)idx * NC + label] = ovv / (a1 + a2 - ovv + 1e-9f);
    }
}

extern "C" void kernel_launch(void* const* d_in, const int* in_sizes, int n_in,
                              void* d_out, int out_size)
{
    const float* anc = (const float*)d_in[0];   // [8400,4]
    const int*   gtl = (const int*)  d_in[1];   // [32,32,1]
    const float* gtb = (const float*)d_in[2];   // [32,32,4]
    const float* mgt = (const float*)d_in[3];   // [32,32,1]
    const float* pd  = (const float*)d_in[4];   // [32,8400,4]

    float* out   = (float*)d_out;
    float* o_lab = out;
    float* o_box = o_lab + (size_t)BSZ * NA;
    float* o_scr = o_box + (size_t)BSZ * NA * 4;
    float* o_fg  = o_scr + (size_t)BSZ * NA * NC;

    const int NS4 = BSZ * NA * NC / 4;
    k_prep<<<(NS4 + 255) / 256, 256>>>(anc, (float4*)o_scr);
    k_pairs<<<(BSZ * NM) / 8, 256>>>(anc, gtb, mgt);
    k_assign<<<(BSZ * NA + 255) / 256, 256>>>(anc, gtl, gtb, pd,
                                              o_lab, o_box, o_scr, o_fg);
}

// round 4
// speedup vs baseline: 2.3651x; 1.7138x over previous
#include <cuda_runtime.h>
#include <cuda_bf16.h>
#include <math.h>

#define NA 8400
#define BSZ 32
#define NM 32
#define NC 80
#define TOPK 9

__device__ unsigned int g_maskpos[BSZ * NA];
__device__ float2       g_ac[NA];               // anchor centers

// Zero score region (float4-coalesced), zero gt bitmask, compute centers.
__global__ __launch_bounds__(256) void k_prep(
    const float* __restrict__ anc, float4* __restrict__ scr4)
{
    const int i = blockIdx.x * blockDim.x + threadIdx.x;
    const int NS4 = BSZ * NA * NC / 4;          // 5,376,000
    if (i < NS4) scr4[i] = make_float4(0.f, 0.f, 0.f, 0.f);
    if (i < BSZ * NA / 4) ((uint4*)g_maskpos)[i] = make_uint4(0u, 0u, 0u, 0u);
    if (i < NA) {
        const float4 ab = ((const float4*)anc)[i];
        g_ac[i] = make_float2((ab.x + ab.z) * 0.5f, (ab.y + ab.w) * 0.5f);
    }
}

// One WARP per (b,g) pair; 8 warps/block. Distance scan is software-pipelined
// (8 independent loads per step -> MLP~8) to hide L1/L2 latency.
__global__ __launch_bounds__(256) void k_pairs(
    const float* __restrict__ anc,
    const float* __restrict__ gtb,
    const float* __restrict__ mask_gt)
{
    __shared__ int s_cand[8][27];

    const int tid  = threadIdx.x;
    const int lane = tid & 31;
    const int w    = tid >> 5;

    const int p = blockIdx.x * 8 + w;
    const int b = p >> 5;
    const int g = p & 31;
    if (mask_gt[p] <= 0.0f) return;             // warp-uniform; no block barriers used

    const float4 gt = ((const float4*)gtb)[p];
    const float gx = (gt.x + gt.z) * 0.5f;
    const float gy = (gt.y + gt.w) * 0.5f;

    const int starts[3] = {0, 6400, 8000};
    const int lens[3]   = {6400, 1600, 400};

    for (int lvl = 0; lvl < 3; ++lvl) {
        unsigned long long kk[TOPK];
        #pragma unroll
        for (int j = 0; j < TOPK; ++j) kk[j] = 0xFFFFFFFFFFFFFFFFull;

        const int start = starts[lvl], L = lens[lvl];

        for (int base = 0; base < L; base += 256) {
            // Batch 8 independent loads (predicated tails read nothing; huge dist)
            float cx[8], cy[8];
            #pragma unroll
            for (int j = 0; j < 8; ++j) {
                const int al = base + j * 32 + lane;
                float2 c = make_float2(1.0e30f, 1.0e30f);
                if (al < L) c = g_ac[start + al];
                cx[j] = c.x; cy[j] = c.y;
            }
            #pragma unroll
            for (int j = 0; j < 8; ++j) {
                const int al = base + j * 32 + lane;
                const float dx = gx - cx[j], dy = gy - cy[j];
                const float d = sqrtf(dx * dx + dy * dy);
                const unsigned long long key =
                    ((unsigned long long)__float_as_uint(d) << 32) |
                    (unsigned int)(start + al);
                if (key < kk[TOPK - 1]) {
                    kk[TOPK - 1] = key;
                    #pragma unroll
                    for (int q = TOPK - 1; q > 0; --q) {
                        if (kk[q] < kk[q - 1]) {
                            const unsigned long long t = kk[q - 1];
                            kk[q - 1] = kk[q]; kk[q] = t;
                        }
                    }
                }
            }
        }

        // 9 rounds of warp-wide u64 min; winning lane pops its head.
        #pragma unroll
        for (int r = 0; r < TOPK; ++r) {
            const unsigned long long v = kk[0];
            unsigned long long m = v;
            #pragma unroll
            for (int s = 16; s > 0; s >>= 1) {
                const unsigned long long o = __shfl_xor_sync(0xffffffffu, m, s);
                if (o < m) m = o;
            }
            if (v == m) {                        // idx bits make keys unique
                #pragma unroll
                for (int j = 0; j < TOPK - 1; ++j) kk[j] = kk[j + 1];
                kk[TOPK - 1] = 0xFFFFFFFFFFFFFFFFull;
            }
            if (lane == 0) s_cand[w][lvl * TOPK + r] = (int)(unsigned int)m;
        }
    }
    __syncwarp();

    // Candidate overlaps (_iou2d: unclipped areas, union eps 1e-6)
    float ov = 0.0f;
    int ca = 0;
    float4 ab = make_float4(0.f, 0.f, 0.f, 0.f);
    if (lane < 27) {
        ca = s_cand[w][lane];
        ab = ((const float4*)anc)[ca];
        const float area1 = (gt.z - gt.x) * (gt.w - gt.y);
        const float area2 = (ab.z - ab.x) * (ab.w - ab.y);
        const float ltx = fmaxf(gt.x, ab.x), lty = fmaxf(gt.y, ab.y);
        const float rbx = fminf(gt.z, ab.z), rby = fminf(gt.w, ab.w);
        const float ww = fmaxf(rbx - ltx, 0.0f), hh = fmaxf(rby - lty, 0.0f);
        const float o = ww * hh;
        ov = o / fmaxf(area1 + area2 - o, 1e-6f);
    }

    // mean + std(ddof=1) threshold via warp sums
    float s = (lane < 27) ? ov : 0.0f;
    #pragma unroll
    for (int sft = 16; sft > 0; sft >>= 1) s += __shfl_xor_sync(0xffffffffu, s, sft);
    const float mean = s * (1.0f / 27.0f);
    float dv = (lane < 27) ? (ov - mean) * (ov - mean) : 0.0f;
    #pragma unroll
    for (int sft = 16; sft > 0; sft >>= 1) dv += __shfl_xor_sync(0xffffffffu, dv, sft);
    const float thr = mean + sqrtf(dv * (1.0f / 26.0f));

    if (lane < 27 && ov > thr) {
        const float ax = (ab.x + ab.z) * 0.5f;
        const float ay = (ab.y + ab.w) * 0.5f;
        const float mn = fminf(fminf(ax - gt.x, ay - gt.y),
                               fminf(gt.z - ax, gt.w - ay));
        if (mn > 1e-9f) atomicOr(&g_maskpos[b * NA + ca], 1u << g);
    }
}

// One thread per (b, anchor): resolve multi-assignment, write outputs.
__global__ __launch_bounds__(256) void k_assign(
    const float* __restrict__ anc,
    const int*   __restrict__ gt_labels,
    const float* __restrict__ gtb,
    const float* __restrict__ pd,
    float* __restrict__ o_lab,
    float* __restrict__ o_box,
    float* __restrict__ o_scr,
    float* __restrict__ o_fg)
{
    const int idx = blockIdx.x * blockDim.x + threadIdx.x;
    if (idx >= BSZ * NA) return;
    const int b = idx / NA;
    const int a = idx - b * NA;

    const unsigned int m = g_maskpos[idx];
    const int cnt = __popc(m);
    int tgt = 0;
    const bool fg = (cnt > 0);

    if (cnt == 1) {
        tgt = __ffs(m) - 1;
    } else if (cnt > 1) {
        // argmax over gts of full overlaps (first-occurrence ties)
        const float4 ab = ((const float4*)anc)[a];
        const float area2 = (ab.z - ab.x) * (ab.w - ab.y);
        float best = -1.0f;
        for (int gg = 0; gg < NM; ++gg) {
            const float4 gb = ((const float4*)gtb)[b * NM + gg];
            const float area1 = (gb.z - gb.x) * (gb.w - gb.y);
            const float ltx = fmaxf(gb.x, ab.x), lty = fmaxf(gb.y, ab.y);
            const float rbx = fminf(gb.z, ab.z), rby = fminf(gb.w, ab.w);
            const float ww = fmaxf(rbx - ltx, 0.0f), hh = fmaxf(rby - lty, 0.0f);
            const float ovv = ww * hh;
            const float v = ovv / fmaxf(area1 + area2 - ovv, 1e-6f);
            if (v > best) { best = v; tgt = gg; }
        }
    }

    const int label = fg ? gt_labels[b * NM + tgt] : NC;
    const float4 tb = ((const float4*)gtb)[b * NM + tgt];

    o_lab[idx] = (float)label;
    ((float4*)o_box)[idx] = tb;
    o_fg[idx] = fg ? 1.0f : 0.0f;

    if (fg) {
        // _iou_batched: clipped areas, +1e-9 in denominator
        const float4 pb = ((const float4*)pd)[(size_t)b * NA + a];
        const float iw = fmaxf(fminf(tb.z, pb.z) - fmaxf(tb.x, pb.x), 0.0f);
        const float ih = fmaxf(fminf(tb.w, pb.w) - fmaxf(tb.y, pb.y), 0.0f);
        const float ovv = iw * ih;
        const float a1 = fmaxf(tb.z - tb.x, 0.0f) * fmaxf(tb.w - tb.y, 0.0f);
        const float a2 = fmaxf(pb.z - pb.x, 0.0f) * fmaxf(pb.w - pb.y, 0.0f);
        o_scr[(size_t)idx * NC + label] = ovv / (a1 + a2 - ovv + 1e-9f);
    }
}

extern "C" void kernel_launch(void* const* d_in, const int* in_sizes, int n_in,
                              void* d_out, int out_size)
{
    const float* anc = (const float*)d_in[0];   // [8400,4]
    const int*   gtl = (const int*)  d_in[1];   // [32,32,1]
    const float* gtb = (const float*)d_in[2];   // [32,32,4]
    const float* mgt = (const float*)d_in[3];   // [32,32,1]
    const float* pd  = (const float*)d_in[4];   // [32,8400,4]

    float* out   = (float*)d_out;
    float* o_lab = out;
    float* o_box = o_lab + (size_t)BSZ * NA;
    float* o_scr = o_box + (size_t)BSZ * NA * 4;
    float* o_fg  = o_scr + (size_t)BSZ * NA * NC;

    const int NS4 = BSZ * NA * NC / 4;
    k_prep<<<(NS4 + 255) / 256, 256>>>(anc, (float4*)o_scr);
    k_pairs<<<(BSZ * NM) / 8, 256>>>(anc, gtb, mgt);
    k_assign<<<(BSZ * NA + 255) / 256, 256>>>(anc, gtl, gtb, pd,
                                              o_lab, o_box, o_scr, o_fg);
}

// round 5
// speedup vs baseline: 2.5208x; 1.0658x over previous
#include <cuda_runtime.h>
#include <cuda_bf16.h>
#include <math.h>

#define NA 8400
#define BSZ 32
#define NM 32
#define NC 80
#define TOPK 9

__device__ unsigned int g_maskpos[BSZ * NA];
__device__ float2       g_ac[NA];               // anchor centers

// Zero score region (float4-coalesced), zero gt bitmask, compute centers.
__global__ __launch_bounds__(256) void k_prep(
    const float* __restrict__ anc, float4* __restrict__ scr4)
{
    const int i = blockIdx.x * blockDim.x + threadIdx.x;
    const int NS4 = BSZ * NA * NC / 4;          // 5,376,000
    if (i < NS4) scr4[i] = make_float4(0.f, 0.f, 0.f, 0.f);
    if (i < BSZ * NA / 4) ((uint4*)g_maskpos)[i] = make_uint4(0u, 0u, 0u, 0u);
    if (i < NA) {
        const float4 ab = ((const float4*)anc)[i];
        g_ac[i] = make_float2((ab.x + ab.z) * 0.5f, (ab.y + ab.w) * 0.5f);
    }
}

// One BLOCK (128 thr = 4 warps) per (b,g) pair. Each warp scans 1/4 of each
// level; 4x9 sorted candidates merge via rank-select; warp 0 does the tail.
__global__ __launch_bounds__(128) void k_pairs(
    const float* __restrict__ anc,
    const float* __restrict__ gtb,
    const float* __restrict__ mask_gt)
{
    __shared__ unsigned long long s_keys[3][36];
    __shared__ int s_cand[27];

    const int tid  = threadIdx.x;
    const int lane = tid & 31;
    const int wq   = tid >> 5;                  // 0..3

    const int p = blockIdx.x;
    const int b = p >> 5;
    const int g = p & 31;
    if (mask_gt[p] <= 0.0f) return;             // block-uniform -> barriers safe

    const float4 gt = ((const float4*)gtb)[p];
    const float gx = (gt.x + gt.z) * 0.5f;
    const float gy = (gt.y + gt.w) * 0.5f;

    const int starts[3] = {0, 6400, 8000};
    const int lens[3]   = {6400, 1600, 400};

    for (int lvl = 0; lvl < 3; ++lvl) {
        unsigned long long kk[TOPK];
        #pragma unroll
        for (int j = 0; j < TOPK; ++j) kk[j] = 0xFFFFFFFFFFFFFFFFull;

        const int start = starts[lvl], L = lens[lvl];

        // This warp's slice: elements wq*32+lane, stride 128; 4-way batched.
        for (int base = wq * 32; base < L; base += 512) {
            float cx[4], cy[4];
            #pragma unroll
            for (int j = 0; j < 4; ++j) {
                const int al = base + j * 128 + lane;
                float2 c = make_float2(1.0e30f, 1.0e30f);
                if (al < L) c = g_ac[start + al];
                cx[j] = c.x; cy[j] = c.y;
            }
            #pragma unroll
            for (int j = 0; j < 4; ++j) {
                const int al = base + j * 128 + lane;
                const float dx = gx - cx[j], dy = gy - cy[j];
                const float d = sqrtf(dx * dx + dy * dy);
                const unsigned long long key =
                    ((unsigned long long)__float_as_uint(d) << 32) |
                    (unsigned int)(start + al);
                if (key < kk[TOPK - 1]) {
                    kk[TOPK - 1] = key;
                    #pragma unroll
                    for (int q = TOPK - 1; q > 0; --q) {
                        if (kk[q] < kk[q - 1]) {
                            const unsigned long long t = kk[q - 1];
                            kk[q - 1] = kk[q]; kk[q] = t;
                        }
                    }
                }
            }
        }

        // Per-warp top-9 extraction: 9 rounds of warp-wide u64 min + pop.
        #pragma unroll
        for (int r = 0; r < TOPK; ++r) {
            const unsigned long long v = kk[0];
            unsigned long long m = v;
            #pragma unroll
            for (int s = 16; s > 0; s >>= 1) {
                const unsigned long long o = __shfl_xor_sync(0xffffffffu, m, s);
                if (o < m) m = o;
            }
            if (v == m) {                        // idx bits make keys unique
                #pragma unroll
                for (int j = 0; j < TOPK - 1; ++j) kk[j] = kk[j + 1];
                kk[TOPK - 1] = 0xFFFFFFFFFFFFFFFFull;
            }
            if (lane == 0) s_keys[lvl][wq * TOPK + r] = m;
        }
    }
    __syncthreads();

    // Warp 0: rank-select top-9 of each level's 36 keys (order irrelevant).
    if (wq == 0) {
        for (int lvl = 0; lvl < 3; ++lvl) {
            #pragma unroll
            for (int half = 0; half < 2; ++half) {
                const int i = lane + half * 32;
                if (i < 36) {
                    const unsigned long long my = s_keys[lvl][i];
                    int rank = 0;
                    #pragma unroll
                    for (int j = 0; j < 36; ++j)
                        rank += (s_keys[lvl][j] < my) ? 1 : 0;
                    if (rank < TOPK)
                        s_cand[lvl * TOPK + rank] = (int)(unsigned int)my;
                }
            }
        }
        __syncwarp();

        // Candidate overlaps (_iou2d: unclipped areas, union eps 1e-6)
        float ov = 0.0f;
        int ca = 0;
        float4 ab = make_float4(0.f, 0.f, 0.f, 0.f);
        if (lane < 27) {
            ca = s_cand[lane];
            ab = ((const float4*)anc)[ca];
            const float area1 = (gt.z - gt.x) * (gt.w - gt.y);
            const float area2 = (ab.z - ab.x) * (ab.w - ab.y);
            const float ltx = fmaxf(gt.x, ab.x), lty = fmaxf(gt.y, ab.y);
            const float rbx = fminf(gt.z, ab.z), rby = fminf(gt.w, ab.w);
            const float ww = fmaxf(rbx - ltx, 0.0f), hh = fmaxf(rby - lty, 0.0f);
            const float o = ww * hh;
            ov = o / fmaxf(area1 + area2 - o, 1e-6f);
        }

        // mean + std(ddof=1) threshold via warp sums
        float s = (lane < 27) ? ov : 0.0f;
        #pragma unroll
        for (int sft = 16; sft > 0; sft >>= 1) s += __shfl_xor_sync(0xffffffffu, s, sft);
        const float mean = s * (1.0f / 27.0f);
        float dv = (lane < 27) ? (ov - mean) * (ov - mean) : 0.0f;
        #pragma unroll
        for (int sft = 16; sft > 0; sft >>= 1) dv += __shfl_xor_sync(0xffffffffu, dv, sft);
        const float thr = mean + sqrtf(dv * (1.0f / 26.0f));

        if (lane < 27 && ov > thr) {
            const float ax = (ab.x + ab.z) * 0.5f;
            const float ay = (ab.y + ab.w) * 0.5f;
            const float mn = fminf(fminf(ax - gt.x, ay - gt.y),
                                   fminf(gt.z - ax, gt.w - ay));
            if (mn > 1e-9f) atomicOr(&g_maskpos[b * NA + ca], 1u << g);
        }
    }
}

// One thread per (b, anchor): resolve multi-assignment, write outputs.
__global__ __launch_bounds__(256) void k_assign(
    const float* __restrict__ anc,
    const int*   __restrict__ gt_labels,
    const float* __restrict__ gtb,
    const float* __restrict__ pd,
    float* __restrict__ o_lab,
    float* __restrict__ o_box,
    float* __restrict__ o_scr,
    float* __restrict__ o_fg)
{
    const int idx = blockIdx.x * blockDim.x + threadIdx.x;
    if (idx >= BSZ * NA) return;
    const int b = idx / NA;
    const int a = idx - b * NA;

    const unsigned int m = g_maskpos[idx];
    const int cnt = __popc(m);
    int tgt = 0;
    const bool fg = (cnt > 0);

    if (cnt == 1) {
        tgt = __ffs(m) - 1;
    } else if (cnt > 1) {
        // argmax over gts of full overlaps (first-occurrence ties)
        const float4 ab = ((const float4*)anc)[a];
        const float area2 = (ab.z - ab.x) * (ab.w - ab.y);
        float best = -1.0f;
        for (int gg = 0; gg < NM; ++gg) {
            const float4 gb = ((const float4*)gtb)[b * NM + gg];
            const float area1 = (gb.z - gb.x) * (gb.w - gb.y);
            const float ltx = fmaxf(gb.x, ab.x), lty = fmaxf(gb.y, ab.y);
            const float rbx = fminf(gb.z, ab.z), rby = fminf(gb.w, ab.w);
            const float ww = fmaxf(rbx - ltx, 0.0f), hh = fmaxf(rby - lty, 0.0f);
            const float ovv = ww * hh;
            const float v = ovv / fmaxf(area1 + area2 - ovv, 1e-6f);
            if (v > best) { best = v; tgt = gg; }
        }
    }

    const int label = fg ? gt_labels[b * NM + tgt] : NC;
    const float4 tb = ((const float4*)gtb)[b * NM + tgt];

    o_lab[idx] = (float)label;
    ((float4*)o_box)[idx] = tb;
    o_fg[idx] = fg ? 1.0f : 0.0f;

    if (fg) {
        // _iou_batched: clipped areas, +1e-9 in denominator
        const float4 pb = ((const float4*)pd)[(size_t)b * NA + a];
        const float iw = fmaxf(fminf(tb.z, pb.z) - fmaxf(tb.x, pb.x), 0.0f);
        const float ih = fmaxf(fminf(tb.w, pb.w) - fmaxf(tb.y, pb.y), 0.0f);
        const float ovv = iw * ih;
        const float a1 = fmaxf(tb.z - tb.x, 0.0f) * fmaxf(tb.w - tb.y, 0.0f);
        const float a2 = fmaxf(pb.z - pb.x, 0.0f) * fmaxf(pb.w - pb.y, 0.0f);
        o_scr[(size_t)idx * NC + label] = ovv / (a1 + a2 - ovv + 1e-9f);
    }
}

extern "C" void kernel_launch(void* const* d_in, const int* in_sizes, int n_in,
                              void* d_out, int out_size)
{
    const float* anc = (const float*)d_in[0];   // [8400,4]
    const int*   gtl = (const int*)  d_in[1];   // [32,32,1]
    const float* gtb = (const float*)d_in[2];   // [32,32,4]
    const float* mgt = (const float*)d_in[3];   // [32,32,1]
    const float* pd  = (const float*)d_in[4];   // [32,8400,4]

    float* out   = (float*)d_out;
    float* o_lab = out;
    float* o_box = o_lab + (size_t)BSZ * NA;
    float* o_scr = o_box + (size_t)BSZ * NA * 4;
    float* o_fg  = o_scr + (size_t)BSZ * NA * NC;

    const int NS4 = BSZ * NA * NC / 4;
    k_prep<<<(NS4 + 255) / 256, 256>>>(anc, (float4*)o_scr);
    k_pairs<<<BSZ * NM, 128>>>(anc, gtb, mgt);
    k_assign<<<(BSZ * NA + 255) / 256, 256>>>(anc, gtl, gtb, pd,
                                              o_lab, o_box, o_scr, o_fg);
}